// round 16
// baseline (speedup 1.0000x reference)
#include <cuda_runtime.h>

#define NN      10000
#define EE      320000
#define IND     32
#define HID     64
#define SEQL    168
#define OUTD    10000
#define COMB    (NN*HID + HID)      // 640064
#define COMB4   (COMB/4)            // 160016
#define RPB     16                  // of1 rows per block
#define CH      37                  // of1 comb chunks (296 blocks = 2/SM; best measured)
#define CAP     128                 // bucket capacity (max degree ~60)

// ---------------- device scratch ----------------
// g_head is zero at module load and re-zeroed at the END of every launch
// (in k_of2, after its last reader) -> always zero at launch entry.
__device__ __align__(16) int   g_head[NN];          // in-degree / fill cursor
__device__ __align__(16) int   g_srcidx[NN * CAP];  // bucketed adjacency
__device__ __align__(16) float g_g[NN * HID];       // dinv[n] * (x@W1^T)[n]  (prescaled)
__device__ __align__(16) float g_a[NN * HID];       // dinv[n] * h2[n]        (prescaled)
__device__ __align__(16) float g_comb[COMB];
__device__ __align__(16) float g_yp[CH * 128];      // of1 partials [chunk][row]

__device__ __forceinline__ float node_dinv(int n) {
    return rsqrtf((float)(g_head[n] + 1));          // +1 self loop
}

// ---------------- bucket fill + weather MLP (block 313) ----------------
__global__ void k_fillW(const int* __restrict__ ei,
                        const float* __restrict__ rain, const float* __restrict__ frain,
                        const float* __restrict__ w1W, const float* __restrict__ w1b,
                        const float* __restrict__ w2W, const float* __restrict__ w2b) {
    int tid = threadIdx.x;
    if (blockIdx.x == 313) {                        // weather branch (independent)
        __shared__ float w[HID];
        if (tid < HID) {
            float s = w1b[tid];
            const float* row = w1W + tid * (SEQL + 1);
            #pragma unroll 4
            for (int k = 0; k < SEQL; k++) s = fmaf(row[k], rain[k], s);
            s = fmaf(row[SEQL], frain[0], s);
            w[tid] = fmaxf(s, 0.f);
        }
        __syncthreads();
        if (tid < HID) {
            float t = w2b[tid];
            const float* r2 = w2W + tid * HID;
            #pragma unroll 8
            for (int k = 0; k < HID; k++) t = fmaf(r2[k], w[k], t);
            g_comb[NN * HID + tid] = t;
        }
        return;
    }
    int i = blockIdx.x * 256 + tid;                 // 313*256 = 80128 >= EE/4
    if (i < EE / 4) {
        int4 s4 = ((const int4*)ei)[i];
        int4 d4 = ((const int4*)(ei + EE))[i];
        int p;
        if ((unsigned)d4.x < NN) { p = atomicAdd(&g_head[d4.x], 1); if (p < CAP) g_srcidx[d4.x * CAP + p] = s4.x; }
        if ((unsigned)d4.y < NN) { p = atomicAdd(&g_head[d4.y], 1); if (p < CAP) g_srcidx[d4.y * CAP + p] = s4.y; }
        if ((unsigned)d4.z < NN) { p = atomicAdd(&g_head[d4.z], 1); if (p < CAP) g_srcidx[d4.z * CAP + p] = s4.z; }
        if ((unsigned)d4.w < NN) { p = atomicAdd(&g_head[d4.w], 1); if (p < CAP) g_srcidx[d4.w * CAP + p] = s4.w; }
    }
}

// ---------------- lin1 (post-fill): g[n,f] = dinv[n] * sum_k x[n,k] W1[f,k] ----------------
__global__ void k_lin1s(const float* __restrict__ x, const float* __restrict__ W) {
    __shared__ float sWf[IND * HID];    // [k][f]
    __shared__ float sx[32][IND];
    int tid = threadIdx.x;
    for (int i = tid; i < HID * IND; i += 256) {
        int f = i >> 5, k = i & 31;
        sWf[k * HID + f] = W[i];
    }
    int node0 = blockIdx.x * 32;
    for (int i = tid; i < 32 * IND; i += 256) {
        int ln = i >> 5, k = i & 31;
        int n = node0 + ln;
        sx[ln][k] = (n < NN) ? x[n * IND + k] : 0.f;
    }
    __syncthreads();
    int fp = tid & 31;
    int grp = tid >> 5;
    const float2* sW2 = (const float2*)sWf;
    float2 a0 = make_float2(0.f, 0.f), a1 = a0, a2 = a0, a3 = a0;
    #pragma unroll
    for (int k = 0; k < IND; k++) {
        float2 w = sW2[k * 32 + fp];
        float x0 = sx[grp * 4 + 0][k];
        float x1 = sx[grp * 4 + 1][k];
        float x2 = sx[grp * 4 + 2][k];
        float x3 = sx[grp * 4 + 3][k];
        a0.x = fmaf(w.x, x0, a0.x); a0.y = fmaf(w.y, x0, a0.y);
        a1.x = fmaf(w.x, x1, a1.x); a1.y = fmaf(w.y, x1, a1.y);
        a2.x = fmaf(w.x, x2, a2.x); a2.y = fmaf(w.y, x2, a2.y);
        a3.x = fmaf(w.x, x3, a3.x); a3.y = fmaf(w.y, x3, a3.y);
    }
    float2* gp = (float2*)g_g;
    int nb = node0 + grp * 4;
    if (nb + 0 < NN) { float d = node_dinv(nb + 0); gp[(nb + 0) * 32 + fp] = make_float2(d * a0.x, d * a0.y); }
    if (nb + 1 < NN) { float d = node_dinv(nb + 1); gp[(nb + 1) * 32 + fp] = make_float2(d * a1.x, d * a1.y); }
    if (nb + 2 < NN) { float d = node_dinv(nb + 2); gp[(nb + 2) * 32 + fp] = make_float2(d * a2.x, d * a2.y); }
    if (nb + 3 < NN) { float d = node_dinv(nb + 3); gp[(nb + 3) * 32 + fp] = make_float2(d * a3.x, d * a3.y); }
}

// ---------------- gather (pure sum, 4-wide — best measured) ----------------
__device__ __forceinline__ float2 gather_s(const float2* __restrict__ gp, int node, int lane) {
    float2 acc = gp[node * 32 + lane];             // self term already dinv-scaled
    int deg = g_head[node]; if (deg > CAP) deg = CAP;
    const int* __restrict__ bk = g_srcidx + node * CAP;
    int e = 0;
    for (; e + 4 <= deg; e += 4) {
        int4 s4 = *(const int4*)(bk + e);          // 16B-aligned (CAP=128)
        float2 v0 = gp[s4.x * 32 + lane];
        float2 v1 = gp[s4.y * 32 + lane];
        float2 v2 = gp[s4.z * 32 + lane];
        float2 v3 = gp[s4.w * 32 + lane];
        acc.x += (v0.x + v1.x) + (v2.x + v3.x);
        acc.y += (v0.y + v1.y) + (v2.y + v3.y);
    }
    for (; e < deg; e++) {
        int s = bk[e];
        float2 v = gp[s * 32 + lane];
        acc.x += v.x; acc.y += v.y;
    }
    return acc;
}

// ---------------- fused agg1 + lin2: 256 thr, 8 nodes/block, 1250 blocks ----------------
// Same shape as agg2 (measured occ 78% there vs 44% in the old 512-thr version).
// Phase A: 8 warps gather 1 node each. Phase B: warps 0-1, 4 nodes/warp, 4x W2 reuse.
__global__ void __launch_bounds__(256)
k_aggLin(const float* __restrict__ b1, const float* __restrict__ W2) {
    __shared__ float sW2t[HID * HID];   // [k][f]
    __shared__ float sa1[8][HID];
    __shared__ float sdn[8];
    int tid = threadIdx.x, lane = tid & 31, wid = tid >> 5;
    for (int i = tid; i < HID * HID; i += 256) {
        int f = i >> 6, k = i & 63;
        sW2t[k * HID + f] = W2[i];
    }
    // Phase A: gather (NN = 1250*8 exactly -> no bounds checks)
    int node = blockIdx.x * 8 + wid;
    {
        float2 acc = gather_s((const float2*)g_g, node, lane);
        float dn = node_dinv(node);
        int f = lane * 2;
        sa1[wid][f]     = fmaxf(fmaf(dn, acc.x, b1[f]),     0.f);
        sa1[wid][f + 1] = fmaxf(fmaf(dn, acc.y, b1[f + 1]), 0.f);
        if (lane == 0) sdn[wid] = dn;
    }
    __syncthreads();
    // Phase B: warps 0-1, each thread = 2 features x 4 nodes (4x W2 LDS reuse)
    if (wid < 2) {
        const float2* sW2v = (const float2*)sW2t;
        const float* r0 = sa1[wid * 4 + 0];
        const float* r1 = sa1[wid * 4 + 1];
        const float* r2 = sa1[wid * 4 + 2];
        const float* r3 = sa1[wid * 4 + 3];
        float2 h0 = make_float2(0.f, 0.f), h1 = h0, h2 = h0, h3 = h0;
        #pragma unroll 8
        for (int k = 0; k < HID; k++) {
            float2 w = sW2v[k * 32 + lane];
            float a0 = r0[k], a1 = r1[k], a2 = r2[k], a3 = r3[k];
            h0.x = fmaf(a0, w.x, h0.x); h0.y = fmaf(a0, w.y, h0.y);
            h1.x = fmaf(a1, w.x, h1.x); h1.y = fmaf(a1, w.y, h1.y);
            h2.x = fmaf(a2, w.x, h2.x); h2.y = fmaf(a2, w.y, h2.y);
            h3.x = fmaf(a3, w.x, h3.x); h3.y = fmaf(a3, w.y, h3.y);
        }
        float2* ga = (float2*)g_a;
        int nb = blockIdx.x * 8 + wid * 4;
        float d0 = sdn[wid * 4 + 0], d1 = sdn[wid * 4 + 1];
        float d2 = sdn[wid * 4 + 2], d3 = sdn[wid * 4 + 3];
        ga[(nb + 0) * 32 + lane] = make_float2(d0 * h0.x, d0 * h0.y);
        ga[(nb + 1) * 32 + lane] = make_float2(d1 * h1.x, d1 * h1.y);
        ga[(nb + 2) * 32 + lane] = make_float2(d2 * h2.x, d2 * h2.y);
        ga[(nb + 3) * 32 + lane] = make_float2(d3 * h3.x, d3 * h3.y);
    }
}

// ---------------- agg2: pure-sum gather, clip [0,10], write comb ----------------
__global__ void k_agg2(const float* __restrict__ b2) {
    int tid = threadIdx.x, lane = tid & 31, wid = tid >> 5;
    int node = blockIdx.x * 8 + wid;
    if (node >= NN) return;
    float2 acc = gather_s((const float2*)g_a, node, lane);
    float dn = node_dinv(node);
    int f = lane * 2;
    float ox = fminf(fmaxf(fmaf(dn, acc.x, b2[f]),     0.f), 10.f);
    float oy = fminf(fmaxf(fmaf(dn, acc.y, b2[f + 1]), 0.f), 10.f);
    ((float2*)g_comb)[node * 32 + lane] = make_float2(ox, oy);
}

// ---------------- of1 matvec: 2 blocks/SM wave, race-free partials ----------------
__global__ void k_of1(const float* __restrict__ W) {
    int r0 = blockIdx.y * RPB;
    const float4* __restrict__ v4 = (const float4*)g_comb;
    const float4* __restrict__ W4 = (const float4*)W;
    float acc[RPB];
    #pragma unroll
    for (int r = 0; r < RPB; r++) acc[r] = 0.f;
    int stride = gridDim.x * blockDim.x;
    for (int i = blockIdx.x * blockDim.x + threadIdx.x; i < COMB4; i += stride) {
        float4 c = v4[i];
        #pragma unroll
        for (int r = 0; r < RPB; r++) {
            float4 a = __ldcs(&W4[(size_t)(r0 + r) * COMB4 + i]);
            acc[r] = fmaf(a.x, c.x, acc[r]);
            acc[r] = fmaf(a.y, c.y, acc[r]);
            acc[r] = fmaf(a.z, c.z, acc[r]);
            acc[r] = fmaf(a.w, c.w, acc[r]);
        }
    }
    int lane = threadIdx.x & 31, wid = threadIdx.x >> 5;
    #pragma unroll
    for (int r = 0; r < RPB; r++) {
        #pragma unroll
        for (int o = 16; o > 0; o >>= 1)
            acc[r] += __shfl_down_sync(0xffffffffu, acc[r], o);
    }
    __shared__ float red[8][RPB];
    if (lane == 0) {
        #pragma unroll
        for (int r = 0; r < RPB; r++) red[wid][r] = acc[r];
    }
    __syncthreads();
    if (threadIdx.x < RPB) {
        float s = 0.f;
        #pragma unroll
        for (int w = 0; w < 8; w++) s += red[w][threadIdx.x];
        g_yp[blockIdx.x * 128 + r0 + threadIdx.x] = s;
    }
}

// ---------------- of2: reduce partials + final projection + re-zero heads ----------------
__global__ void k_of2(const float* __restrict__ of1b, const float* __restrict__ of2W,
                      const float* __restrict__ of2b, float* __restrict__ out) {
    int tid = threadIdx.x;
    // restore launch-entry invariant for next call (heads' last reader was agg2)
    int z = blockIdx.x * 256 + tid;                  // grid is exactly 40 blocks
    if (z < NN) g_head[z] = 0;
    __shared__ float so[128];
    if (tid < 128) {
        float s = of1b[tid];
        #pragma unroll
        for (int c = 0; c < CH; c++) s += g_yp[c * 128 + tid];
        so[tid] = fmaxf(s, 0.f);
    }
    __syncthreads();
    int k = blockIdx.x * 256 + tid;
    if (k < OUTD) {
        const float4* __restrict__ w4 = (const float4*)(of2W + (size_t)k * 128);
        float s = of2b[k];
        #pragma unroll
        for (int j = 0; j < 32; j++) {
            float4 a = __ldg(&w4[j]);
            s = fmaf(a.x, so[j * 4 + 0], s);
            s = fmaf(a.y, so[j * 4 + 1], s);
            s = fmaf(a.z, so[j * 4 + 2], s);
            s = fmaf(a.w, so[j * 4 + 3], s);
        }
        out[k] = s;
    }
}

// ---------------- host ----------------
extern "C" void kernel_launch(void* const* d_in, const int* in_sizes, int n_in,
                              void* d_out, int out_size) {
    const float* x     = (const float*)d_in[0];
    const int*   ei    = (const int*)d_in[1];
    const float* rain  = (const float*)d_in[2];
    const float* frain = (const float*)d_in[3];
    const float* W1    = (const float*)d_in[4];
    const float* b1    = (const float*)d_in[5];
    const float* W2    = (const float*)d_in[6];
    const float* b2    = (const float*)d_in[7];
    const float* wf1W  = (const float*)d_in[8];
    const float* wf1b  = (const float*)d_in[9];
    const float* wf2W  = (const float*)d_in[10];
    const float* wf2b  = (const float*)d_in[11];
    const float* of1W  = (const float*)d_in[12];
    const float* of1b  = (const float*)d_in[13];
    const float* of2W  = (const float*)d_in[14];
    const float* of2b  = (const float*)d_in[15];
    float* out = (float*)d_out;

    k_fillW <<<314, 256>>>(ei, rain, frain, wf1W, wf1b, wf2W, wf2b); // buckets + weather
    k_lin1s <<<(NN + 31) / 32, 256>>>(x, W1);                        // prescaled h1
    k_aggLin<<<NN / 8, 256>>>(b1, W2);                               // agg2-shaped, 8 nodes/block
    k_agg2  <<<(NN + 7) / 8, 256>>>(b2);                             // gather -> comb
    k_of1   <<<dim3(CH, 8), 256>>>(of1W);                            // 2 blocks/SM wave
    k_of2   <<<(OUTD + 255) / 256, 256>>>(of1b, of2W, of2b, out);    // + re-zero heads
}

// round 17
// speedup vs baseline: 1.1394x; 1.1394x over previous
#include <cuda_runtime.h>

#define NN      10000
#define EE      320000
#define IND     32
#define HID     64
#define SEQL    168
#define OUTD    10000
#define COMB    (NN*HID + HID)      // 640064
#define COMB4   (COMB/4)            // 160016
#define RPB     16                  // of1 rows per block
#define CH      37                  // of1 comb chunks (296 blocks = 2/SM; best measured)
#define CAP     128                 // bucket capacity (max degree ~60)

// ---------------- device scratch ----------------
// g_head is zero at module load and re-zeroed at the END of every launch
// (in k_of2, after its last reader) -> always zero at launch entry.
__device__ __align__(16) int   g_head[NN];          // in-degree / fill cursor
__device__ __align__(16) int   g_srcidx[NN * CAP];  // bucketed adjacency
__device__ __align__(16) float g_g[NN * HID];       // dinv[n] * (x@W1^T)[n]  (prescaled)
__device__ __align__(16) float g_a[NN * HID];       // dinv[n] * h2[n]        (prescaled)
__device__ __align__(16) float g_comb[COMB];
__device__ __align__(16) float g_yp[CH * 128];      // of1 partials [chunk][row]

__device__ __forceinline__ float node_dinv(int n) {
    return rsqrtf((float)(g_head[n] + 1));          // +1 self loop
}

// ---------------- bucket fill (8 edges/thread) + weather MLP (block 157) ----------------
__global__ void k_fillW(const int* __restrict__ ei,
                        const float* __restrict__ rain, const float* __restrict__ frain,
                        const float* __restrict__ w1W, const float* __restrict__ w1b,
                        const float* __restrict__ w2W, const float* __restrict__ w2b) {
    int tid = threadIdx.x;
    if (blockIdx.x == 157) {                        // weather branch (independent)
        __shared__ float w[HID];
        if (tid < HID) {
            float s = w1b[tid];
            const float* row = w1W + tid * (SEQL + 1);
            #pragma unroll 4
            for (int k = 0; k < SEQL; k++) s = fmaf(row[k], rain[k], s);
            s = fmaf(row[SEQL], frain[0], s);
            w[tid] = fmaxf(s, 0.f);
        }
        __syncthreads();
        if (tid < HID) {
            float t = w2b[tid];
            const float* r2 = w2W + tid * HID;
            #pragma unroll 8
            for (int k = 0; k < HID; k++) t = fmaf(r2[k], w[k], t);
            g_comb[NN * HID + tid] = t;
        }
        return;
    }
    int i = blockIdx.x * 256 + tid;                 // i < EE/8 = 40000 (157*256 = 40192)
    if (i < EE / 8) {
        const int4* s8 = (const int4*)ei + i * 2;
        const int4* d8 = (const int4*)(ei + EE) + i * 2;
        int4 sa = s8[0], sb = s8[1];
        int4 da = d8[0], db = d8[1];
        int p;
        if ((unsigned)da.x < NN) { p = atomicAdd(&g_head[da.x], 1); if (p < CAP) g_srcidx[da.x * CAP + p] = sa.x; }
        if ((unsigned)da.y < NN) { p = atomicAdd(&g_head[da.y], 1); if (p < CAP) g_srcidx[da.y * CAP + p] = sa.y; }
        if ((unsigned)da.z < NN) { p = atomicAdd(&g_head[da.z], 1); if (p < CAP) g_srcidx[da.z * CAP + p] = sa.z; }
        if ((unsigned)da.w < NN) { p = atomicAdd(&g_head[da.w], 1); if (p < CAP) g_srcidx[da.w * CAP + p] = sa.w; }
        if ((unsigned)db.x < NN) { p = atomicAdd(&g_head[db.x], 1); if (p < CAP) g_srcidx[db.x * CAP + p] = sb.x; }
        if ((unsigned)db.y < NN) { p = atomicAdd(&g_head[db.y], 1); if (p < CAP) g_srcidx[db.y * CAP + p] = sb.y; }
        if ((unsigned)db.z < NN) { p = atomicAdd(&g_head[db.z], 1); if (p < CAP) g_srcidx[db.z * CAP + p] = sb.z; }
        if ((unsigned)db.w < NN) { p = atomicAdd(&g_head[db.w], 1); if (p < CAP) g_srcidx[db.w * CAP + p] = sb.w; }
    }
}

// ---------------- lin1 (post-fill): g[n,f] = dinv[n] * sum_k x[n,k] W1[f,k] ----------------
__global__ void k_lin1s(const float* __restrict__ x, const float* __restrict__ W) {
    __shared__ float sWf[IND * HID];    // [k][f]
    __shared__ float sx[32][IND];
    int tid = threadIdx.x;
    for (int i = tid; i < HID * IND; i += 256) {
        int f = i >> 5, k = i & 31;
        sWf[k * HID + f] = W[i];
    }
    int node0 = blockIdx.x * 32;
    for (int i = tid; i < 32 * IND; i += 256) {
        int ln = i >> 5, k = i & 31;
        int n = node0 + ln;
        sx[ln][k] = (n < NN) ? x[n * IND + k] : 0.f;
    }
    __syncthreads();
    int fp = tid & 31;
    int grp = tid >> 5;
    const float2* sW2 = (const float2*)sWf;
    float2 a0 = make_float2(0.f, 0.f), a1 = a0, a2 = a0, a3 = a0;
    #pragma unroll
    for (int k = 0; k < IND; k++) {
        float2 w = sW2[k * 32 + fp];
        float x0 = sx[grp * 4 + 0][k];
        float x1 = sx[grp * 4 + 1][k];
        float x2 = sx[grp * 4 + 2][k];
        float x3 = sx[grp * 4 + 3][k];
        a0.x = fmaf(w.x, x0, a0.x); a0.y = fmaf(w.y, x0, a0.y);
        a1.x = fmaf(w.x, x1, a1.x); a1.y = fmaf(w.y, x1, a1.y);
        a2.x = fmaf(w.x, x2, a2.x); a2.y = fmaf(w.y, x2, a2.y);
        a3.x = fmaf(w.x, x3, a3.x); a3.y = fmaf(w.y, x3, a3.y);
    }
    float2* gp = (float2*)g_g;
    int nb = node0 + grp * 4;
    if (nb + 0 < NN) { float d = node_dinv(nb + 0); gp[(nb + 0) * 32 + fp] = make_float2(d * a0.x, d * a0.y); }
    if (nb + 1 < NN) { float d = node_dinv(nb + 1); gp[(nb + 1) * 32 + fp] = make_float2(d * a1.x, d * a1.y); }
    if (nb + 2 < NN) { float d = node_dinv(nb + 2); gp[(nb + 2) * 32 + fp] = make_float2(d * a2.x, d * a2.y); }
    if (nb + 3 < NN) { float d = node_dinv(nb + 3); gp[(nb + 3) * 32 + fp] = make_float2(d * a3.x, d * a3.y); }
}

// ---------------- gather (pure sum, 4-wide — best measured) ----------------
__device__ __forceinline__ float2 gather_s(const float2* __restrict__ gp, int node, int lane) {
    float2 acc = gp[node * 32 + lane];             // self term already dinv-scaled
    int deg = g_head[node]; if (deg > CAP) deg = CAP;
    const int* __restrict__ bk = g_srcidx + node * CAP;
    int e = 0;
    for (; e + 4 <= deg; e += 4) {
        int4 s4 = *(const int4*)(bk + e);          // 16B-aligned (CAP=128)
        float2 v0 = gp[s4.x * 32 + lane];
        float2 v1 = gp[s4.y * 32 + lane];
        float2 v2 = gp[s4.z * 32 + lane];
        float2 v3 = gp[s4.w * 32 + lane];
        acc.x += (v0.x + v1.x) + (v2.x + v3.x);
        acc.y += (v0.y + v1.y) + (v2.y + v3.y);
    }
    for (; e < deg; e++) {
        int s = bk[e];
        float2 v = gp[s * 32 + lane];
        acc.x += v.x; acc.y += v.y;
    }
    return acc;
}

// ---------------- fused agg1 + lin2: 512 thr, 2 blocks/SM, two-phase (R15 best) ----------------
__global__ void __launch_bounds__(512, 2)
k_aggLin(const float* __restrict__ b1, const float* __restrict__ W2) {
    __shared__ float sW2t[HID * HID];   // [k][f]
    __shared__ float sa1[16][HID];
    __shared__ float sdn[16];
    int tid = threadIdx.x, lane = tid & 31, wid = tid >> 5;
    for (int i = tid; i < HID * HID; i += 512) {
        int f = i >> 6, k = i & 63;
        sW2t[k * HID + f] = W2[i];
    }
    // Phase A: gather (NN = 625*16 exactly)
    int node = blockIdx.x * 16 + wid;
    {
        float2 acc = gather_s((const float2*)g_g, node, lane);
        float dn = node_dinv(node);
        int f = lane * 2;
        sa1[wid][f]     = fmaxf(fmaf(dn, acc.x, b1[f]),     0.f);
        sa1[wid][f + 1] = fmaxf(fmaf(dn, acc.y, b1[f + 1]), 0.f);
        if (lane == 0) sdn[wid] = dn;
    }
    __syncthreads();
    // Phase B: warps 0-3, each thread = 2 features x 4 nodes (4x W2 LDS reuse)
    if (wid < 4) {
        const float2* sW2v = (const float2*)sW2t;
        const float* r0 = sa1[wid * 4 + 0];
        const float* r1 = sa1[wid * 4 + 1];
        const float* r2 = sa1[wid * 4 + 2];
        const float* r3 = sa1[wid * 4 + 3];
        float2 h0 = make_float2(0.f, 0.f), h1 = h0, h2 = h0, h3 = h0;
        #pragma unroll 8
        for (int k = 0; k < HID; k++) {
            float2 w = sW2v[k * 32 + lane];
            float a0 = r0[k], a1 = r1[k], a2 = r2[k], a3 = r3[k];
            h0.x = fmaf(a0, w.x, h0.x); h0.y = fmaf(a0, w.y, h0.y);
            h1.x = fmaf(a1, w.x, h1.x); h1.y = fmaf(a1, w.y, h1.y);
            h2.x = fmaf(a2, w.x, h2.x); h2.y = fmaf(a2, w.y, h2.y);
            h3.x = fmaf(a3, w.x, h3.x); h3.y = fmaf(a3, w.y, h3.y);
        }
        float2* ga = (float2*)g_a;
        int nb = blockIdx.x * 16 + wid * 4;
        float d0 = sdn[wid * 4 + 0], d1 = sdn[wid * 4 + 1];
        float d2 = sdn[wid * 4 + 2], d3 = sdn[wid * 4 + 3];
        ga[(nb + 0) * 32 + lane] = make_float2(d0 * h0.x, d0 * h0.y);
        ga[(nb + 1) * 32 + lane] = make_float2(d1 * h1.x, d1 * h1.y);
        ga[(nb + 2) * 32 + lane] = make_float2(d2 * h2.x, d2 * h2.y);
        ga[(nb + 3) * 32 + lane] = make_float2(d3 * h3.x, d3 * h3.y);
    }
}

// ---------------- agg2: pure-sum gather, clip [0,10], write comb ----------------
__global__ void k_agg2(const float* __restrict__ b2) {
    int tid = threadIdx.x, lane = tid & 31, wid = tid >> 5;
    int node = blockIdx.x * 8 + wid;
    if (node >= NN) return;
    float2 acc = gather_s((const float2*)g_a, node, lane);
    float dn = node_dinv(node);
    int f = lane * 2;
    float ox = fminf(fmaxf(fmaf(dn, acc.x, b2[f]),     0.f), 10.f);
    float oy = fminf(fmaxf(fmaf(dn, acc.y, b2[f + 1]), 0.f), 10.f);
    ((float2*)g_comb)[node * 32 + lane] = make_float2(ox, oy);
}

// ---------------- of1 matvec: 2 blocks/SM wave, race-free partials ----------------
__global__ void k_of1(const float* __restrict__ W) {
    int r0 = blockIdx.y * RPB;
    const float4* __restrict__ v4 = (const float4*)g_comb;
    const float4* __restrict__ W4 = (const float4*)W;
    float acc[RPB];
    #pragma unroll
    for (int r = 0; r < RPB; r++) acc[r] = 0.f;
    int stride = gridDim.x * blockDim.x;
    for (int i = blockIdx.x * blockDim.x + threadIdx.x; i < COMB4; i += stride) {
        float4 c = v4[i];
        #pragma unroll
        for (int r = 0; r < RPB; r++) {
            float4 a = __ldcs(&W4[(size_t)(r0 + r) * COMB4 + i]);
            acc[r] = fmaf(a.x, c.x, acc[r]);
            acc[r] = fmaf(a.y, c.y, acc[r]);
            acc[r] = fmaf(a.z, c.z, acc[r]);
            acc[r] = fmaf(a.w, c.w, acc[r]);
        }
    }
    int lane = threadIdx.x & 31, wid = threadIdx.x >> 5;
    #pragma unroll
    for (int r = 0; r < RPB; r++) {
        #pragma unroll
        for (int o = 16; o > 0; o >>= 1)
            acc[r] += __shfl_down_sync(0xffffffffu, acc[r], o);
    }
    __shared__ float red[8][RPB];
    if (lane == 0) {
        #pragma unroll
        for (int r = 0; r < RPB; r++) red[wid][r] = acc[r];
    }
    __syncthreads();
    if (threadIdx.x < RPB) {
        float s = 0.f;
        #pragma unroll
        for (int w = 0; w < 8; w++) s += red[w][threadIdx.x];
        g_yp[blockIdx.x * 128 + r0 + threadIdx.x] = s;
    }
}

// ---------------- of2: reduce partials + final projection + re-zero heads ----------------
__global__ void k_of2(const float* __restrict__ of1b, const float* __restrict__ of2W,
                      const float* __restrict__ of2b, float* __restrict__ out) {
    int tid = threadIdx.x;
    // restore launch-entry invariant for next call (heads' last reader was agg2)
    int z = blockIdx.x * 256 + tid;                  // grid is exactly 40 blocks
    if (z < NN) g_head[z] = 0;
    __shared__ float so[128];
    if (tid < 128) {
        float s = of1b[tid];
        #pragma unroll
        for (int c = 0; c < CH; c++) s += g_yp[c * 128 + tid];
        so[tid] = fmaxf(s, 0.f);
    }
    __syncthreads();
    int k = blockIdx.x * 256 + tid;
    if (k < OUTD) {
        const float4* __restrict__ w4 = (const float4*)(of2W + (size_t)k * 128);
        float s = of2b[k];
        #pragma unroll
        for (int j = 0; j < 32; j++) {
            float4 a = __ldg(&w4[j]);
            s = fmaf(a.x, so[j * 4 + 0], s);
            s = fmaf(a.y, so[j * 4 + 1], s);
            s = fmaf(a.z, so[j * 4 + 2], s);
            s = fmaf(a.w, so[j * 4 + 3], s);
        }
        out[k] = s;
    }
}

// ---------------- host ----------------
extern "C" void kernel_launch(void* const* d_in, const int* in_sizes, int n_in,
                              void* d_out, int out_size) {
    const float* x     = (const float*)d_in[0];
    const int*   ei    = (const int*)d_in[1];
    const float* rain  = (const float*)d_in[2];
    const float* frain = (const float*)d_in[3];
    const float* W1    = (const float*)d_in[4];
    const float* b1    = (const float*)d_in[5];
    const float* W2    = (const float*)d_in[6];
    const float* b2    = (const float*)d_in[7];
    const float* wf1W  = (const float*)d_in[8];
    const float* wf1b  = (const float*)d_in[9];
    const float* wf2W  = (const float*)d_in[10];
    const float* wf2b  = (const float*)d_in[11];
    const float* of1W  = (const float*)d_in[12];
    const float* of1b  = (const float*)d_in[13];
    const float* of2W  = (const float*)d_in[14];
    const float* of2b  = (const float*)d_in[15];
    float* out = (float*)d_out;

    k_fillW <<<158, 256>>>(ei, rain, frain, wf1W, wf1b, wf2W, wf2b); // 8 edges/thr + weather
    k_lin1s <<<(NN + 31) / 32, 256>>>(x, W1);                        // prescaled h1
    k_aggLin<<<NN / 16, 512>>>(b1, W2);                              // R15-best two-phase
    k_agg2  <<<(NN + 7) / 8, 256>>>(b2);                             // gather -> comb
    k_of1   <<<dim3(CH, 8), 256>>>(of1W);                            // 2 blocks/SM wave
    k_of2   <<<(OUTD + 255) / 256, 256>>>(of1b, of2W, of2b, out);    // + re-zero heads
}